// round 2
// baseline (speedup 1.0000x reference)
#include <cuda_runtime.h>
#include <math.h>
#include <stdint.h>

#define BB 16
#define GG 100
#define PP 8400
#define CC 80
#define TK 13

// ---------------- static scratch (no allocations allowed) ----------------
__device__ int           d_fgpre[BB * PP];
__device__ int           d_mcount[BB * PP];
__device__ int           d_mg[BB * PP];
__device__ unsigned char d_valid[BB * PP];

// ---------------- small sorted-list helpers (register resident) ----------
template <int N>
__device__ __forceinline__ void ins_desc(float (&V)[N], int (&I)[N], float v, int idx) {
    // keep N best by (value desc, idx asc)  == jax.lax.top_k tie-break
    if (v > V[N - 1] || (v == V[N - 1] && idx < I[N - 1])) {
#pragma unroll
        for (int k = 0; k < N; k++) {
            if (v > V[k] || (v == V[k] && idx < I[k])) {
                float tv = V[k]; int ti = I[k];
                V[k] = v; I[k] = idx;
                v = tv; idx = ti;
            }
        }
    }
}

template <int N>
__device__ __forceinline__ void ins_asc(float (&V)[N], int (&I)[N], float v, int idx) {
    // keep N best by (value asc, idx asc)  == stable argsort prefix
    if (v < V[N - 1] || (v == V[N - 1] && idx < I[N - 1])) {
#pragma unroll
        for (int k = 0; k < N; k++) {
            if (v < V[k] || (v == V[k] && idx < I[k])) {
                float tv = V[k]; int ti = I[k];
                V[k] = v; I[k] = idx;
                v = tv; idx = ti;
            }
        }
    }
}

template <int N>
__device__ __forceinline__ void ins_val(float (&V)[N], float v) {
    // values only, descending (for top-13 iou sum)
    if (v > V[N - 1]) {
#pragma unroll
        for (int k = 0; k < N; k++) {
            if (v > V[k]) { float tv = V[k]; V[k] = v; v = tv; }
        }
    }
}

// ---------------- kernels ----------------
__global__ void zero_kernel(int n) {
    int i = blockIdx.x * blockDim.x + threadIdx.x;
    if (i < n) { d_fgpre[i] = 0; d_mcount[i] = 0; }
}

__global__ void valid_kernel(const float* __restrict__ priors,
                             const float* __restrict__ gtb,
                             const float* __restrict__ pad,
                             int Pn, int Gn) {
    int b = blockIdx.y;
    __shared__ float sgt[GG * 4];
    __shared__ float spad[GG];
    for (int i = threadIdx.x; i < Gn * 4; i += blockDim.x) sgt[i] = gtb[b * Gn * 4 + i];
    for (int i = threadIdx.x; i < Gn; i += blockDim.x)     spad[i] = pad[b * Gn + i];
    __syncthreads();
    int p = blockIdx.x * blockDim.x + threadIdx.x;
    if (p >= Pn) return;
    float px = priors[p * 4 + 0];
    float py = priors[p * 4 + 1];
    unsigned char v = 0;
    for (int g = 0; g < Gn; g++) {
        if (spad[g] != 0.0f) {
            float x1 = sgt[g * 4 + 0], y1 = sgt[g * 4 + 1];
            float x2 = sgt[g * 4 + 2], y2 = sgt[g * 4 + 3];
            if (px > x1 && py > y1 && px < x2 && py < y2) { v = 1; break; }
        }
    }
    d_valid[b * Pn + p] = v;
}

// one block per (gt g, batch b) that has pad==1
__global__ __launch_bounds__(128) void pair_kernel(
    const float* __restrict__ pred_bboxes,
    const float* __restrict__ pred_scores,
    const float* __restrict__ priors,
    const int*   __restrict__ gt_labels,
    const float* __restrict__ gt_bboxes,
    const float* __restrict__ pad,
    int Pn, int Gn, int Cn) {
    int g = blockIdx.x, b = blockIdx.y;
    if (pad[b * Gn + g] == 0.0f) return;

    const float gx1 = gt_bboxes[(b * Gn + g) * 4 + 0];
    const float gy1 = gt_bboxes[(b * Gn + g) * 4 + 1];
    const float gx2 = gt_bboxes[(b * Gn + g) * 4 + 2];
    const float gy2 = gt_bboxes[(b * Gn + g) * 4 + 3];
    const int   cid = gt_labels[b * Gn + g];
    const float ga  = (gx2 - gx1) * (gy2 - gy1);
    const float cx  = (gx1 + gx2) * 0.5f;
    const float cy  = (gy1 + gy2) * 0.5f;

    const float*         pb = pred_bboxes + (size_t)b * Pn * 4;
    const float*         sc = pred_scores + (size_t)b * Pn * Cn + cid;
    const unsigned char* vm = d_valid + b * Pn;
    const int tid = threadIdx.x;
    const float INFF = __int_as_float(0x7f800000);

    float mv[TK], iv[TK], cv[TK];
    int   mi[TK], ci[TK];
#pragma unroll
    for (int k = 0; k < TK; k++) {
        mv[k] = -INFF; mi[k] = 0x7fffffff;
        iv[k] = -INFF;
        cv[k] =  INFF; ci[k] = 0x7fffffff;
    }

    for (int p = tid; p < Pn; p += 128) {
        float4 pbx = reinterpret_cast<const float4*>(pb)[p];
        float pa = (pbx.z - pbx.x) * (pbx.w - pbx.y);
        float w  = fmaxf(fminf(gx2, pbx.z) - fmaxf(gx1, pbx.x), 0.0f);
        float h  = fmaxf(fminf(gy2, pbx.w) - fmaxf(gy1, pbx.y), 0.0f);
        float inter = w * h;
        float uni   = fmaxf(ga + pa - inter, 1e-6f);
        float iou   = inter / uni;

        float4 pr = reinterpret_cast<const float4*>(priors)[p];
        bool ing = (pr.x > gx1) && (pr.y > gy1) && (pr.x < gx2) && (pr.y < gy2);

        float x   = sc[(size_t)p * Cn];
        float ax  = fabsf(x);
        float t   = expf(-ax);
        float inv = 1.0f / (1.0f + t);
        float sig = (x >= 0.0f) ? inv : t * inv;

        float i2 = iou * iou;
        float i6 = i2 * i2 * i2;
        float metric = ing ? sig * i6 : 0.0f;
        ins_desc(mv, mi, metric, p);
        ins_val(iv, iou);

        float cost;
        if (vm[p]) {
            float sp   = fmaxf(x, 0.0f) + log1pf(t);       // logaddexp(0,x)
            float sca  = iou - sig;
            float cls  = (sp - x * iou) * (sca * sca);
            float icst = -3.0f * logf(iou + 1e-7f);
            float dx = pr.x - cx, dy = pr.y - cy;
            float dist = sqrtf(dx * dx + dy * dy) / pr.z;
            float scp  = expf((dist - 3.0f) * 2.302585092994046f);  // 10^(dist-3)
            cost = cls + icst + scp;
        } else {
            cost = 1e8f;   // INF sentinel from reference (valid-but-far priors can be +inf > 1e8)
        }
        ins_asc(cv, ci, cost, p);
    }

    // -------- block-level merges (tree over 128 sorted lists) --------
    __shared__ float s_v[128 * TK];
    __shared__ int   s_i[128 * TK];
    __shared__ int   s_ks;

    // 1) metrics top-13 (desc, idx-asc ties)
#pragma unroll
    for (int k = 0; k < TK; k++) { s_v[tid * TK + k] = mv[k]; s_i[tid * TK + k] = mi[k]; }
    __syncthreads();
    for (int off = 64; off >= 1; off >>= 1) {
        if (tid < off) {
            float ov[TK]; int oi[TK];
            int ia = tid * TK, ib = (tid + off) * TK, i = 0, j = 0;
#pragma unroll
            for (int k = 0; k < TK; k++) {
                float va = s_v[ia + i], vb = s_v[ib + j];
                int   na = s_i[ia + i], nb = s_i[ib + j];
                bool ta = (va > vb) || (va == vb && na < nb);
                if (ta) { ov[k] = va; oi[k] = na; i++; }
                else    { ov[k] = vb; oi[k] = nb; j++; }
            }
#pragma unroll
            for (int k = 0; k < TK; k++) { s_v[ia + k] = ov[k]; s_i[ia + k] = oi[k]; }
        }
        __syncthreads();
    }
    if (tid < TK) {  // pos_mask contribution: topk & in_gts & pad -> fg_pre
        int p = s_i[tid];
        float px = priors[p * 4 + 0], py = priors[p * 4 + 1];
        if (px > gx1 && py > gy1 && px < gx2 && py < gy2)
            atomicAdd(&d_fgpre[b * Pn + p], 1);
    }
    __syncthreads();

    // 2) iou top-13 values -> dynamic_ks
#pragma unroll
    for (int k = 0; k < TK; k++) s_v[tid * TK + k] = iv[k];
    __syncthreads();
    for (int off = 64; off >= 1; off >>= 1) {
        if (tid < off) {
            float ov[TK];
            int ia = tid * TK, ib = (tid + off) * TK, i = 0, j = 0;
#pragma unroll
            for (int k = 0; k < TK; k++) {
                float va = s_v[ia + i], vb = s_v[ib + j];
                if (va >= vb) { ov[k] = va; i++; } else { ov[k] = vb; j++; }
            }
#pragma unroll
            for (int k = 0; k < TK; k++) s_v[ia + k] = ov[k];
        }
        __syncthreads();
    }
    if (tid == 0) {
        float sum = 0.0f;
#pragma unroll
        for (int k = 0; k < TK; k++) sum += s_v[k];
        int ks = (int)sum;               // trunc like astype(int32)
        if (ks < 1) ks = 1;
        if (ks > TK) ks = TK;
        s_ks = ks;
    }
    __syncthreads();

    // 3) cost min-13 (asc, idx-asc ties) -> matching scatter
#pragma unroll
    for (int k = 0; k < TK; k++) { s_v[tid * TK + k] = cv[k]; s_i[tid * TK + k] = ci[k]; }
    __syncthreads();
    for (int off = 64; off >= 1; off >>= 1) {
        if (tid < off) {
            float ov[TK]; int oi[TK];
            int ia = tid * TK, ib = (tid + off) * TK, i = 0, j = 0;
#pragma unroll
            for (int k = 0; k < TK; k++) {
                float va = s_v[ia + i], vb = s_v[ib + j];
                int   na = s_i[ia + i], nb = s_i[ib + j];
                bool ta = (va < vb) || (va == vb && na < nb);
                if (ta) { ov[k] = va; oi[k] = na; i++; }
                else    { ov[k] = vb; oi[k] = nb; j++; }
            }
#pragma unroll
            for (int k = 0; k < TK; k++) { s_v[ia + k] = ov[k]; s_i[ia + k] = oi[k]; }
        }
        __syncthreads();
    }
    if (tid < s_ks) {
        int p = s_i[tid];
        atomicAdd(&d_mcount[b * Pn + p], 1);
        d_mg[b * Pn + p] = g;   // only consumed when count==1 (single writer)
    }
}

__device__ __forceinline__ float cost_of_pair(
    float iou, float x, float px, float py, float s, float cx, float cy) {
    float ax  = fabsf(x);
    float t   = expf(-ax);
    float inv = 1.0f / (1.0f + t);
    float sig = (x >= 0.0f) ? inv : t * inv;
    float sp  = fmaxf(x, 0.0f) + log1pf(t);
    float sca = iou - sig;
    float cls = (sp - x * iou) * (sca * sca);
    float icst = -3.0f * logf(iou + 1e-7f);
    float dx = px - cx, dy = py - cy;
    float dist = sqrtf(dx * dx + dy * dy) / s;
    float scp  = expf((dist - 3.0f) * 2.302585092994046f);
    return cls + icst + scp;
}

__global__ void final_kernel(
    const float* __restrict__ pred_bboxes,
    const float* __restrict__ pred_scores,
    const float* __restrict__ priors,
    const int*   __restrict__ gt_labels,
    const float* __restrict__ gt_bboxes,
    float* __restrict__ out,
    int Pn, int Gn, int Cn, int Bn) {
    int p = blockIdx.x * blockDim.x + threadIdx.x;
    int b = blockIdx.y;
    if (p >= Pn) return;
    int bp = b * Pn + p;
    int BP = Bn * Pn;

    int cnt = d_mcount[bp];
    float lab = 80.0f, metr = 0.0f;
    float ox0 = 0.f, ox1 = 0.f, ox2 = 0.f, ox3 = 0.f;

    if (cnt > 0) {
        int gsel;
        if (cnt == 1) {
            gsel = d_mg[bp];
        } else if (!d_valid[bp]) {
            gsel = 0;  // all costs tie at 1e8 -> first argmin
        } else {
            float4 pbx = reinterpret_cast<const float4*>(pred_bboxes + (size_t)b * Pn * 4)[p];
            float pa = (pbx.z - pbx.x) * (pbx.w - pbx.y);
            float px = priors[p * 4 + 0], py = priors[p * 4 + 1], s = priors[p * 4 + 2];
            const float* srow = pred_scores + ((size_t)b * Pn + p) * Cn;
            float best = 0.0f; int bg = 0;
            for (int g = 0; g < Gn; g++) {
                float gx1 = gt_bboxes[(b * Gn + g) * 4 + 0];
                float gy1 = gt_bboxes[(b * Gn + g) * 4 + 1];
                float gx2 = gt_bboxes[(b * Gn + g) * 4 + 2];
                float gy2 = gt_bboxes[(b * Gn + g) * 4 + 3];
                float gaa = (gx2 - gx1) * (gy2 - gy1);
                float w = fmaxf(fminf(gx2, pbx.z) - fmaxf(gx1, pbx.x), 0.0f);
                float h = fmaxf(fminf(gy2, pbx.w) - fmaxf(gy1, pbx.y), 0.0f);
                float inter = w * h;
                float iou = inter / fmaxf(gaa + pa - inter, 1e-6f);
                float x = srow[gt_labels[b * Gn + g]];
                float c = cost_of_pair(iou, x, px, py, s,
                                       (gx1 + gx2) * 0.5f, (gy1 + gy2) * 0.5f);
                if (g == 0 || c < best) { best = c; bg = g; }
            }
            gsel = bg;
        }
        // gather outputs for matched gt
        float gx1 = gt_bboxes[(b * Gn + gsel) * 4 + 0];
        float gy1 = gt_bboxes[(b * Gn + gsel) * 4 + 1];
        float gx2 = gt_bboxes[(b * Gn + gsel) * 4 + 2];
        float gy2 = gt_bboxes[(b * Gn + gsel) * 4 + 3];
        float4 pbx = reinterpret_cast<const float4*>(pred_bboxes + (size_t)b * Pn * 4)[p];
        float pa = (pbx.z - pbx.x) * (pbx.w - pbx.y);
        float gaa = (gx2 - gx1) * (gy2 - gy1);
        float w = fmaxf(fminf(gx2, pbx.z) - fmaxf(gx1, pbx.x), 0.0f);
        float h = fmaxf(fminf(gy2, pbx.w) - fmaxf(gy1, pbx.y), 0.0f);
        float inter = w * h;
        float iou = inter / fmaxf(gaa + pa - inter, 1e-6f);

        lab = (float)gt_labels[b * Gn + gsel];
        metr = iou;
        ox0 = gx1; ox1 = gy1; ox2 = gx2; ox3 = gy2;
    }

    out[bp]            = lab;                       // assigned_labels
    out[BP + bp]       = 1.0f;                      // assigned_labels_weights
    out[2 * BP + (size_t)bp * 4 + 0] = ox0;         // assigned_bboxes
    out[2 * BP + (size_t)bp * 4 + 1] = ox1;
    out[2 * BP + (size_t)bp * 4 + 2] = ox2;
    out[2 * BP + (size_t)bp * 4 + 3] = ox3;
    out[6 * BP + bp]   = metr;                      // assign_metrics
    out[7 * BP + bp]   = (d_fgpre[bp] > 0) ? 1.0f : 0.0f;  // fg_mask_pre_prior
}

// ---------------- launch ----------------
extern "C" void kernel_launch(void* const* d_in, const int* in_sizes, int n_in,
                              void* d_out, int out_size) {
    const float* pred_bboxes = (const float*)d_in[0];
    const float* pred_scores = (const float*)d_in[1];
    const float* priors      = (const float*)d_in[2];
    const int*   gt_labels   = (const int*)  d_in[3];
    const float* gt_bboxes   = (const float*)d_in[4];
    const float* pad         = (const float*)d_in[5];

    int P = in_sizes[2] / 4;
    int B = in_sizes[0] / (P * 4);
    int G = in_sizes[4] / (B * 4);
    int C = in_sizes[1] / (B * P);
    float* out = (float*)d_out;

    int n = B * P;
    zero_kernel<<<(n + 255) / 256, 256>>>(n);

    dim3 gv((P + 255) / 256, B);
    valid_kernel<<<gv, 256>>>(priors, gt_bboxes, pad, P, G);

    dim3 gp(G, B);
    pair_kernel<<<gp, 128>>>(pred_bboxes, pred_scores, priors,
                             gt_labels, gt_bboxes, pad, P, G, C);

    dim3 gf((P + 127) / 128, B);
    final_kernel<<<gf, 128>>>(pred_bboxes, pred_scores, priors,
                              gt_labels, gt_bboxes, out, P, G, C, B);
}

// round 5
// speedup vs baseline: 1.0765x; 1.0765x over previous
#include <cuda_runtime.h>
#include <math.h>
#include <stdint.h>

#define BB 16
#define GG 100
#define PP 8400
#define CC 80
#define TK 13

// ---------------- static scratch ----------------
__device__ int           d_fgpre[BB * PP];
__device__ int           d_mcount[BB * PP];
__device__ int           d_mg[BB * PP];
__device__ unsigned char d_valid[BB * PP];

// ---------------- sorted-list helpers ----------
template <int N>
__device__ __forceinline__ void ins_desc(float (&V)[N], int (&I)[N], float v, int idx) {
    if (v > V[N - 1] || (v == V[N - 1] && idx < I[N - 1])) {
#pragma unroll
        for (int k = 0; k < N; k++) {
            if (v > V[k] || (v == V[k] && idx < I[k])) {
                float tv = V[k]; int ti = I[k];
                V[k] = v; I[k] = idx;
                v = tv; idx = ti;
            }
        }
    }
}

template <int N>
__device__ __forceinline__ void ins_asc(float (&V)[N], int (&I)[N], float v, int idx) {
    if (v < V[N - 1] || (v == V[N - 1] && idx < I[N - 1])) {
#pragma unroll
        for (int k = 0; k < N; k++) {
            if (v < V[k] || (v == V[k] && idx < I[k])) {
                float tv = V[k]; int ti = I[k];
                V[k] = v; I[k] = idx;
                v = tv; idx = ti;
            }
        }
    }
}

template <int N>
__device__ __forceinline__ void ins_val(float (&V)[N], float v) {
    if (v > V[N - 1]) {
#pragma unroll
        for (int k = 0; k < N; k++) {
            if (v > V[k]) { float tv = V[k]; V[k] = v; v = tv; }
        }
    }
}

// rr2 such that skip iff d2 > rr2*s2 guarantees cost >= thr (can't improve list)
__device__ __forceinline__ float skip_radius2(float thr) {
    // cost >= scp - 3e-7, scp = 10^(dist-3). Skip when 10^(dist-3) - 3e-7 >= thr.
    // dist >= 3 + log10(thr + 1e-6) + 1e-3 (conservative margins).
    float rr = 3.0f + log10f(thr + 1e-6f) + 1e-3f;   // thr=inf -> rr=inf -> never skip
    if (rr > 0.0f) return rr * rr;
    // rr <= 0: thr ~<= 1e-3. If thr < 9e-4, even dist=0 has cost >= 1e-3-3e-7 > thr.
    return (thr < 9e-4f) ? -1.0f : __int_as_float(0x7f800000);
}

// ---------------- kernels ----------------
__global__ void valid_kernel(const float* __restrict__ priors,
                             const float* __restrict__ gtb,
                             const float* __restrict__ pad,
                             int Pn, int Gn) {
    int b = blockIdx.y;
    __shared__ float sgt[GG * 4];
    __shared__ float spad[GG];
    for (int i = threadIdx.x; i < Gn * 4; i += blockDim.x) sgt[i] = gtb[b * Gn * 4 + i];
    for (int i = threadIdx.x; i < Gn; i += blockDim.x)     spad[i] = pad[b * Gn + i];
    __syncthreads();
    int p = blockIdx.x * blockDim.x + threadIdx.x;
    if (p >= Pn) return;
    float px = priors[p * 4 + 0];
    float py = priors[p * 4 + 1];
    unsigned char v = 0;
    for (int g = 0; g < Gn; g++) {
        if (spad[g] != 0.0f) {
            float x1 = sgt[g * 4 + 0], y1 = sgt[g * 4 + 1];
            float x2 = sgt[g * 4 + 2], y2 = sgt[g * 4 + 3];
            if (px > x1 && py > y1 && px < x2 && py < y2) { v = 1; break; }
        }
    }
    int bp = b * Pn + p;
    d_valid[bp]  = v;
    d_fgpre[bp]  = 0;
    d_mcount[bp] = 0;
}

// one block per (gt g, batch b) with pad==1
__global__ __launch_bounds__(128, 4) void pair_kernel(
    const float* __restrict__ pred_bboxes,
    const float* __restrict__ pred_scores,
    const float* __restrict__ priors,
    const int*   __restrict__ gt_labels,
    const float* __restrict__ gt_bboxes,
    const float* __restrict__ pad,
    int Pn, int Gn, int Cn) {
    int g = blockIdx.x, b = blockIdx.y;
    if (pad[b * Gn + g] == 0.0f) return;

    const float gx1 = gt_bboxes[(b * Gn + g) * 4 + 0];
    const float gy1 = gt_bboxes[(b * Gn + g) * 4 + 1];
    const float gx2 = gt_bboxes[(b * Gn + g) * 4 + 2];
    const float gy2 = gt_bboxes[(b * Gn + g) * 4 + 3];
    const int   cid = gt_labels[b * Gn + g];
    const float ga  = (gx2 - gx1) * (gy2 - gy1);
    const float cx  = (gx1 + gx2) * 0.5f;
    const float cy  = (gy1 + gy2) * 0.5f;

    const float*         pb = pred_bboxes + (size_t)b * Pn * 4;
    const float*         sc = pred_scores + (size_t)b * Pn * Cn + cid;
    const unsigned char* vm = d_valid + b * Pn;
    const int tid = threadIdx.x;
    const float INFF = __int_as_float(0x7f800000);

    float mv[TK], iv[TK], cv[TK];
    int   mi[TK], ci[TK];
#pragma unroll
    for (int k = 0; k < TK; k++) {
        mv[k] = -INFF; mi[k] = 0x7fffffff;
        iv[k] = -INFF;
        cv[k] =  INFF; ci[k] = 0x7fffffff;
    }
    float thr = INFF;
    float rr2 = INFF;   // never skip until list fills

    for (int p = tid; p < Pn; p += 128) {
        float4 pbx = reinterpret_cast<const float4*>(pb)[p];
        float pa = (pbx.z - pbx.x) * (pbx.w - pbx.y);
        float w  = fmaxf(fminf(gx2, pbx.z) - fmaxf(gx1, pbx.x), 0.0f);
        float h  = fmaxf(fminf(gy2, pbx.w) - fmaxf(gy1, pbx.y), 0.0f);
        float inter = w * h;
        float iou   = inter / fmaxf(ga + pa - inter, 1e-6f);
        ins_val(iv, iou);

        float4 pr = reinterpret_cast<const float4*>(priors)[p];
        bool ing = (pr.x > gx1) && (pr.y > gy1) && (pr.x < gx2) && (pr.y < gy2);

        bool vmp = (vm[p] != 0);
        bool docost = false;
        float d2 = 0.0f;
        if (vmp) {
            float dx = pr.x - cx, dy = pr.y - cy;
            d2 = dx * dx + dy * dy;
            docost = !(d2 > rr2 * (pr.z * pr.z));   // skip only if provably >= thr
        }

        float metric = 0.0f;
        if (ing || docost) {
            float x   = sc[(size_t)p * Cn];
            float ax  = fabsf(x);
            float t   = expf(-ax);
            float inv = 1.0f / (1.0f + t);
            float sig = (x >= 0.0f) ? inv : t * inv;
            if (ing) {
                float i2 = iou * iou;
                metric = sig * (i2 * i2 * i2);
            }
            if (docost) {
                float sp   = fmaxf(x, 0.0f) + log1pf(t);       // logaddexp(0,x)
                float sca  = iou - sig;
                float cls  = (sp - x * iou) * (sca * sca);
                float icst = -3.0f * logf(iou + 1e-7f);
                float dist = sqrtf(d2) / pr.z;
                float scp  = expf((dist - 3.0f) * 2.302585092994046f);  // 10^(dist-3)
                ins_asc(cv, ci, cls + icst + scp, p);
            }
        }
        ins_desc(mv, mi, metric, p);

        if (!vmp) ins_asc(cv, ci, 1e8f, p);   // INF sentinel from reference

        float nthr = cv[TK - 1];
        if (nthr != thr) { thr = nthr; rr2 = skip_radius2(thr); }
    }

    // -------- block-level merges (tree over 128 sorted lists) --------
    __shared__ float s_v[128 * TK];
    __shared__ int   s_i[128 * TK];
    __shared__ int   s_ks;

    // 1) metrics top-13 (desc, idx-asc ties)
#pragma unroll
    for (int k = 0; k < TK; k++) { s_v[tid * TK + k] = mv[k]; s_i[tid * TK + k] = mi[k]; }
    __syncthreads();
    for (int off = 64; off >= 1; off >>= 1) {
        if (tid < off) {
            float ov[TK]; int oi[TK];
            int ia = tid * TK, ib = (tid + off) * TK, i = 0, j = 0;
#pragma unroll
            for (int k = 0; k < TK; k++) {
                float va = s_v[ia + i], vb = s_v[ib + j];
                int   na = s_i[ia + i], nb = s_i[ib + j];
                bool ta = (va > vb) || (va == vb && na < nb);
                if (ta) { ov[k] = va; oi[k] = na; i++; }
                else    { ov[k] = vb; oi[k] = nb; j++; }
            }
#pragma unroll
            for (int k = 0; k < TK; k++) { s_v[ia + k] = ov[k]; s_i[ia + k] = oi[k]; }
        }
        __syncthreads();
    }
    if (tid < TK) {  // pos_mask: topk & in_gts -> fg_pre
        int p = s_i[tid];
        float px = priors[p * 4 + 0], py = priors[p * 4 + 1];
        if (px > gx1 && py > gy1 && px < gx2 && py < gy2)
            atomicAdd(&d_fgpre[b * Pn + p], 1);
    }
    __syncthreads();

    // 2) iou top-13 values -> dynamic_ks
#pragma unroll
    for (int k = 0; k < TK; k++) s_v[tid * TK + k] = iv[k];
    __syncthreads();
    for (int off = 64; off >= 1; off >>= 1) {
        if (tid < off) {
            float ov[TK];
            int ia = tid * TK, ib = (tid + off) * TK, i = 0, j = 0;
#pragma unroll
            for (int k = 0; k < TK; k++) {
                float va = s_v[ia + i], vb = s_v[ib + j];
                if (va >= vb) { ov[k] = va; i++; } else { ov[k] = vb; j++; }
            }
#pragma unroll
            for (int k = 0; k < TK; k++) s_v[ia + k] = ov[k];
        }
        __syncthreads();
    }
    if (tid == 0) {
        float sum = 0.0f;
#pragma unroll
        for (int k = 0; k < TK; k++) sum += s_v[k];
        int ks = (int)sum;
        if (ks < 1) ks = 1;
        if (ks > TK) ks = TK;
        s_ks = ks;
    }
    __syncthreads();

    // 3) cost min-13 (asc, idx-asc ties) -> matching scatter
#pragma unroll
    for (int k = 0; k < TK; k++) { s_v[tid * TK + k] = cv[k]; s_i[tid * TK + k] = ci[k]; }
    __syncthreads();
    for (int off = 64; off >= 1; off >>= 1) {
        if (tid < off) {
            float ov[TK]; int oi[TK];
            int ia = tid * TK, ib = (tid + off) * TK, i = 0, j = 0;
#pragma unroll
            for (int k = 0; k < TK; k++) {
                float va = s_v[ia + i], vb = s_v[ib + j];
                int   na = s_i[ia + i], nb = s_i[ib + j];
                bool ta = (va < vb) || (va == vb && na < nb);
                if (ta) { ov[k] = va; oi[k] = na; i++; }
                else    { ov[k] = vb; oi[k] = nb; j++; }
            }
#pragma unroll
            for (int k = 0; k < TK; k++) { s_v[ia + k] = ov[k]; s_i[ia + k] = oi[k]; }
        }
        __syncthreads();
    }
    if (tid < s_ks) {
        int p = s_i[tid];
        atomicAdd(&d_mcount[b * Pn + p], 1);
        d_mg[b * Pn + p] = g;   // consumed only when count==1
    }
}

__device__ __forceinline__ float cost_of_pair(
    float iou, float x, float d2, float s, float /*unused*/) {
    float ax  = fabsf(x);
    float t   = expf(-ax);
    float inv = 1.0f / (1.0f + t);
    float sig = (x >= 0.0f) ? inv : t * inv;
    float sp  = fmaxf(x, 0.0f) + log1pf(t);
    float sca = iou - sig;
    float cls = (sp - x * iou) * (sca * sca);
    float icst = -3.0f * logf(iou + 1e-7f);
    float dist = sqrtf(d2) / s;
    float scp  = expf((dist - 3.0f) * 2.302585092994046f);
    return cls + icst + scp;
}

__global__ __launch_bounds__(128) void final_kernel(
    const float* __restrict__ pred_bboxes,
    const float* __restrict__ pred_scores,
    const float* __restrict__ priors,
    const int*   __restrict__ gt_labels,
    const float* __restrict__ gt_bboxes,
    float* __restrict__ out,
    int Pn, int Gn, int Cn, int Bn) {
    int b = blockIdx.y;
    __shared__ float4 sgt[GG];
    __shared__ int    slab[GG];
    for (int i = threadIdx.x; i < Gn; i += blockDim.x) {
        sgt[i]  = reinterpret_cast<const float4*>(gt_bboxes + (size_t)b * Gn * 4)[i];
        slab[i] = gt_labels[b * Gn + i];
    }
    __syncthreads();

    int p = blockIdx.x * blockDim.x + threadIdx.x;
    if (p >= Pn) return;
    int bp = b * Pn + p;
    int BP = Bn * Pn;

    int cnt = d_mcount[bp];
    float lab = 80.0f, metr = 0.0f;
    float ox0 = 0.f, ox1 = 0.f, ox2 = 0.f, ox3 = 0.f;

    if (cnt > 0) {
        float4 pbx = reinterpret_cast<const float4*>(pred_bboxes + (size_t)b * Pn * 4)[p];
        float pa = (pbx.z - pbx.x) * (pbx.w - pbx.y);
        int gsel;
        if (cnt == 1) {
            gsel = d_mg[bp];
        } else if (!d_valid[bp]) {
            gsel = 0;  // all costs tie at 1e8 -> first argmin
        } else {
            float px = priors[p * 4 + 0], py = priors[p * 4 + 1], s = priors[p * 4 + 2];
            float s2 = s * s;
            const float* srow = pred_scores + ((size_t)b * Pn + p) * Cn;
            float best = __int_as_float(0x7f800000);
            float rr2  = __int_as_float(0x7f800000);
            int bg = 0;
            for (int g = 0; g < Gn; g++) {
                float4 gb = sgt[g];
                float gcx = (gb.x + gb.z) * 0.5f, gcy = (gb.y + gb.w) * 0.5f;
                float dx = px - gcx, dy = py - gcy;
                float d2 = dx * dx + dy * dy;
                if (d2 > rr2 * s2) continue;     // cost >= best, keep earlier g
                float gaa = (gb.z - gb.x) * (gb.w - gb.y);
                float w = fmaxf(fminf(gb.z, pbx.z) - fmaxf(gb.x, pbx.x), 0.0f);
                float h = fmaxf(fminf(gb.w, pbx.w) - fmaxf(gb.y, pbx.y), 0.0f);
                float inter = w * h;
                float iou = inter / fmaxf(gaa + pa - inter, 1e-6f);
                float x = srow[slab[g]];
                float c = cost_of_pair(iou, x, d2, s, 0.0f);
                if (c < best) { best = c; bg = g; rr2 = skip_radius2(best); }
            }
            gsel = bg;
        }
        // gather outputs for matched gt
        float4 gb = sgt[gsel];
        float gaa = (gb.z - gb.x) * (gb.w - gb.y);
        float w = fmaxf(fminf(gb.z, pbx.z) - fmaxf(gb.x, pbx.x), 0.0f);
        float h = fmaxf(fminf(gb.w, pbx.w) - fmaxf(gb.y, pbx.y), 0.0f);
        float inter = w * h;
        float iou = inter / fmaxf(gaa + pa - inter, 1e-6f);

        lab = (float)slab[gsel];
        metr = iou;
        ox0 = gb.x; ox1 = gb.y; ox2 = gb.z; ox3 = gb.w;
    }

    out[bp]            = lab;
    out[BP + bp]       = 1.0f;
    out[2 * BP + (size_t)bp * 4 + 0] = ox0;
    out[2 * BP + (size_t)bp * 4 + 1] = ox1;
    out[2 * BP + (size_t)bp * 4 + 2] = ox2;
    out[2 * BP + (size_t)bp * 4 + 3] = ox3;
    out[6 * BP + bp]   = metr;
    out[7 * BP + bp]   = (d_fgpre[bp] > 0) ? 1.0f : 0.0f;
}

// ---------------- launch ----------------
extern "C" void kernel_launch(void* const* d_in, const int* in_sizes, int n_in,
                              void* d_out, int out_size) {
    const float* pred_bboxes = (const float*)d_in[0];
    const float* pred_scores = (const float*)d_in[1];
    const float* priors      = (const float*)d_in[2];
    const int*   gt_labels   = (const int*)  d_in[3];
    const float* gt_bboxes   = (const float*)d_in[4];
    const float* pad         = (const float*)d_in[5];

    int P = in_sizes[2] / 4;
    int B = in_sizes[0] / (P * 4);
    int G = in_sizes[4] / (B * 4);
    int C = in_sizes[1] / (B * P);
    float* out = (float*)d_out;

    dim3 gv((P + 255) / 256, B);
    valid_kernel<<<gv, 256>>>(priors, gt_bboxes, pad, P, G);

    dim3 gp(G, B);
    pair_kernel<<<gp, 128>>>(pred_bboxes, pred_scores, priors,
                             gt_labels, gt_bboxes, pad, P, G, C);

    dim3 gf((P + 127) / 128, B);
    final_kernel<<<gf, 128>>>(pred_bboxes, pred_scores, priors,
                              gt_labels, gt_bboxes, out, P, G, C, B);
}

// round 6
// speedup vs baseline: 1.9702x; 1.8301x over previous
#include <cuda_runtime.h>
#include <math.h>
#include <stdint.h>

#define BB 16
#define GG 100
#define PP 8400
#define CC 80
#define TK 13
#define NBIN 64
#define NCHMAX ((PP + 31) / 32)

// ---------------- static scratch ----------------
__device__ int           d_fgpre[BB * PP];
__device__ int           d_mcount[BB * PP];
__device__ int           d_mg[BB * PP];
__device__ unsigned char d_valid[BB * PP];
__device__ float4        d_sorted[BB * PP];
__device__ float4        d_cmeta[BB * NCHMAX];
__device__ int           d_bincnt[BB * NBIN];
__device__ int           d_inv13[BB * TK];
__device__ int           d_invcnt[BB];

// ---------------- sorted-list helpers ----------
template <int N>
__device__ __forceinline__ void ins_desc(float (&V)[N], int (&I)[N], float v, int idx) {
    if (v > V[N - 1] || (v == V[N - 1] && idx < I[N - 1])) {
#pragma unroll
        for (int k = 0; k < N; k++) {
            if (v > V[k] || (v == V[k] && idx < I[k])) {
                float tv = V[k]; int ti = I[k];
                V[k] = v; I[k] = idx;
                v = tv; idx = ti;
            }
        }
    }
}

template <int N>
__device__ __forceinline__ void ins_asc(float (&V)[N], int (&I)[N], float v, int idx) {
    if (v < V[N - 1] || (v == V[N - 1] && idx < I[N - 1])) {
#pragma unroll
        for (int k = 0; k < N; k++) {
            if (v < V[k] || (v == V[k] && idx < I[k])) {
                float tv = V[k]; int ti = I[k];
                V[k] = v; I[k] = idx;
                v = tv; idx = ti;
            }
        }
    }
}

template <int N>
__device__ __forceinline__ void ins_val(float (&V)[N], float v) {
    if (v > V[N - 1]) {
#pragma unroll
        for (int k = 0; k < N; k++) {
            if (v > V[k]) { float tv = V[k]; V[k] = v; v = tv; }
        }
    }
}

__device__ __forceinline__ float skip_radius2(float thr) {
    float rr = 3.0f + log10f(thr + 1e-6f) + 1e-3f;
    if (rr > 0.0f) return rr * rr;
    return (thr < 9e-4f) ? -1.0f : __int_as_float(0x7f800000);
}

__device__ __forceinline__ int binof(float4 t) {
    float xc = 0.5f * (t.x + t.z);
    int b = (int)(xc * (NBIN / 640.0f));
    return min(NBIN - 1, max(0, b));
}

// ---------------- prep kernels ----------------
__global__ void zerobins_kernel() {
    int i = blockIdx.x * blockDim.x + threadIdx.x;
    if (i < BB * NBIN) d_bincnt[i] = 0;
}

__global__ void valid_kernel(const float* __restrict__ priors,
                             const float* __restrict__ gtb,
                             const float* __restrict__ pad,
                             const float* __restrict__ pred_bboxes,
                             int Pn, int Gn) {
    int b = blockIdx.y;
    __shared__ float sgt[GG * 4];
    __shared__ float spad[GG];
    for (int i = threadIdx.x; i < Gn * 4; i += blockDim.x) sgt[i] = gtb[b * Gn * 4 + i];
    for (int i = threadIdx.x; i < Gn; i += blockDim.x)     spad[i] = pad[b * Gn + i];
    __syncthreads();
    int p = blockIdx.x * blockDim.x + threadIdx.x;
    if (p >= Pn) return;
    float px = priors[p * 4 + 0];
    float py = priors[p * 4 + 1];
    unsigned char v = 0;
    for (int g = 0; g < Gn; g++) {
        if (spad[g] != 0.0f) {
            float x1 = sgt[g * 4 + 0], y1 = sgt[g * 4 + 1];
            float x2 = sgt[g * 4 + 2], y2 = sgt[g * 4 + 3];
            if (px > x1 && py > y1 && px < x2 && py < y2) { v = 1; break; }
        }
    }
    int bp = b * Pn + p;
    d_valid[bp]  = v;
    d_fgpre[bp]  = 0;
    d_mcount[bp] = 0;
    // bin count for spatial sort of pred boxes
    float4 t = reinterpret_cast<const float4*>(pred_bboxes)[(size_t)b * Pn + p];
    atomicAdd(&d_bincnt[b * NBIN + binof(t)], 1);
}

__global__ void inv13_kernel(int Pn) {
    int b = blockIdx.x, tid = threadIdx.x;
    int lst[TK]; int cnt = 0;
    for (int p = tid; p < Pn && cnt < TK; p += 128)
        if (!d_valid[b * Pn + p]) lst[cnt++] = p;
#pragma unroll
    for (int k = 0; k < TK; k++) if (k >= cnt) lst[k] = 0x7fffffff;
    __shared__ int s_i[128 * TK];
#pragma unroll
    for (int k = 0; k < TK; k++) s_i[tid * TK + k] = lst[k];
    __syncthreads();
    for (int off = 64; off >= 1; off >>= 1) {
        if (tid < off) {
            int oi[TK];
            int ia = tid * TK, ib = (tid + off) * TK, i = 0, j = 0;
#pragma unroll
            for (int k = 0; k < TK; k++) {
                int na = s_i[ia + i], nb = s_i[ib + j];
                if (na <= nb) { oi[k] = na; i++; } else { oi[k] = nb; j++; }
            }
#pragma unroll
            for (int k = 0; k < TK; k++) s_i[ia + k] = oi[k];
        }
        __syncthreads();
    }
    if (tid == 0) {
        int S = 0;
#pragma unroll
        for (int k = 0; k < TK; k++) {
            d_inv13[b * TK + k] = s_i[k];
            if (s_i[k] != 0x7fffffff) S++;
        }
        d_invcnt[b] = S;
    }
}

__global__ void sortscatter_kernel(const float* __restrict__ pred_bboxes, int Pn) {
    int b = blockIdx.x, tid = threadIdx.x;
    __shared__ int cur[NBIN];
    if (tid == 0) {
        int acc = 0;
        for (int i = 0; i < NBIN; i++) { int c = d_bincnt[b * NBIN + i]; cur[i] = acc; acc += c; }
    }
    __syncthreads();
    const float4* pb = reinterpret_cast<const float4*>(pred_bboxes) + (size_t)b * Pn;
    for (int p = tid; p < Pn; p += blockDim.x) {
        float4 t = pb[p];
        int pos = atomicAdd(&cur[binof(t)], 1);
        d_sorted[b * Pn + pos] = t;
    }
}

__global__ void meta_kernel(int Pn) {
    int c = blockIdx.x, b = blockIdx.y, lane = threadIdx.x;
    int p = c * 32 + lane;
    const float INFF = __int_as_float(0x7f800000);
    float x1 = INFF, y1 = INFF, x2 = -INFF, y2 = -INFF;
    if (p < Pn) {
        float4 t = d_sorted[b * Pn + p];
        x1 = t.x; y1 = t.y; x2 = t.z; y2 = t.w;
    }
#pragma unroll
    for (int off = 16; off >= 1; off >>= 1) {
        x1 = fminf(x1, __shfl_down_sync(0xffffffffu, x1, off));
        y1 = fminf(y1, __shfl_down_sync(0xffffffffu, y1, off));
        x2 = fmaxf(x2, __shfl_down_sync(0xffffffffu, x2, off));
        y2 = fmaxf(y2, __shfl_down_sync(0xffffffffu, y2, off));
    }
    if (lane == 0) d_cmeta[b * NCHMAX + c] = make_float4(x1, y1, x2, y2);
}

// ---------------- main pair kernel ----------------
__global__ __launch_bounds__(128) void pair_kernel(
    const float* __restrict__ pred_bboxes,
    const float* __restrict__ pred_scores,
    const float* __restrict__ priors,
    const int*   __restrict__ gt_labels,
    const float* __restrict__ gt_bboxes,
    const float* __restrict__ pad,
    int Pn, int Gn, int Cn, int nch) {
    int g = blockIdx.x, b = blockIdx.y;
    if (pad[b * Gn + g] == 0.0f) return;

    const float gx1 = gt_bboxes[(b * Gn + g) * 4 + 0];
    const float gy1 = gt_bboxes[(b * Gn + g) * 4 + 1];
    const float gx2 = gt_bboxes[(b * Gn + g) * 4 + 2];
    const float gy2 = gt_bboxes[(b * Gn + g) * 4 + 3];
    const int   cid = gt_labels[b * Gn + g];
    const float ga  = (gx2 - gx1) * (gy2 - gy1);
    const float cx  = (gx1 + gx2) * 0.5f;
    const float cy  = (gy1 + gy2) * 0.5f;

    const float4*        pb  = reinterpret_cast<const float4*>(pred_bboxes) + (size_t)b * Pn;
    const float4*        pr4 = reinterpret_cast<const float4*>(priors);
    const float*         sc  = pred_scores + (size_t)b * Pn * Cn + cid;
    const unsigned char* vm  = d_valid + b * Pn;
    const int tid = threadIdx.x;
    const int warp = tid >> 5, lane = tid & 31;
    const float INFF = __int_as_float(0x7f800000);

    __shared__ float s_v[128 * TK];
    __shared__ int   s_i[128 * TK];
    __shared__ int   s_ks;
    __shared__ int   s_npos;

    // ======== Phase 1: top-13 iou over sorted, chunk-skipped preds ========
    {
        float iv[TK];
#pragma unroll
        for (int k = 0; k < TK; k++) iv[k] = -INFF;
        const float4* sp = d_sorted + (size_t)b * Pn;
        const float4* cm = d_cmeta + b * NCHMAX;
        for (int c = warp; c < nch; c += 4) {
            float4 m = cm[c];
            if (m.x < gx2 && m.z > gx1 && m.y < gy2 && m.w > gy1) {
                int p = c * 32 + lane;
                if (p < Pn) {
                    float4 t = sp[p];
                    float pa = (t.z - t.x) * (t.w - t.y);
                    float w = fmaxf(fminf(gx2, t.z) - fmaxf(gx1, t.x), 0.0f);
                    float h = fmaxf(fminf(gy2, t.w) - fmaxf(gy1, t.y), 0.0f);
                    float inter = w * h;
                    float iou = __fdividef(inter, fmaxf(ga + pa - inter, 1e-6f));
                    ins_val(iv, iou);
                }
            }
        }
#pragma unroll
        for (int k = 0; k < TK; k++) s_v[tid * TK + k] = iv[k];
        __syncthreads();
        for (int off = 64; off >= 1; off >>= 1) {
            if (tid < off) {
                float ov[TK];
                int ia = tid * TK, ib = (tid + off) * TK, i = 0, j = 0;
#pragma unroll
                for (int k = 0; k < TK; k++) {
                    float va = s_v[ia + i], vb = s_v[ib + j];
                    if (va >= vb) { ov[k] = va; i++; } else { ov[k] = vb; j++; }
                }
#pragma unroll
                for (int k = 0; k < TK; k++) s_v[ia + k] = ov[k];
            }
            __syncthreads();
        }
        if (tid == 0) {
            float sum = 0.0f;
#pragma unroll
            for (int k = 0; k < TK; k++) sum += fmaxf(s_v[k], 0.0f);  // skipped pairs are iou==0
            int ks = (int)sum;
            if (ks < 1) ks = 1;
            if (ks > TK) ks = TK;
            s_ks = ks;
        }
        __syncthreads();
    }

    const int   LW[3] = {80, 40, 20};
    const float LS[3] = {8.0f, 16.0f, 32.0f};
    const int   LBASE[3] = {0, 6400, 8000};

    // ======== Phase 2: metric top-13 via gt-box grid rectangle ========
    {
        float mv[TK]; int mi[TK];
#pragma unroll
        for (int k = 0; k < TK; k++) { mv[k] = -INFF; mi[k] = 0x7fffffff; }
#pragma unroll
        for (int lvl = 0; lvl < 3; lvl++) {
            int W = LW[lvl]; float s = LS[lvl]; int base = LBASE[lvl];
            float inv_s = 1.0f / s;
            int c0 = max(0, (int)floorf(gx1 * inv_s - 0.5f));
            int c1 = min(W - 1, (int)ceilf(gx2 * inv_s - 0.5f));
            int r0 = max(0, (int)floorf(gy1 * inv_s - 0.5f));
            int r1 = min(W - 1, (int)ceilf(gy2 * inv_s - 0.5f));
            int nc = c1 - c0 + 1, nr = r1 - r0 + 1;
            if (nc <= 0 || nr <= 0) continue;
            int tot = nc * nr;
            for (int i = tid; i < tot; i += 128) {
                int rr = i / nc, cc = i - rr * nc;
                int col = c0 + cc, row = r0 + rr;
                float px = ((float)col + 0.5f) * s;
                float py = ((float)row + 0.5f) * s;
                if (px > gx1 && px < gx2 && py > gy1 && py < gy2) {
                    int p = base + row * W + col;
                    float4 t = pb[p];
                    float pa = (t.z - t.x) * (t.w - t.y);
                    float w = fmaxf(fminf(gx2, t.z) - fmaxf(gx1, t.x), 0.0f);
                    float h = fmaxf(fminf(gy2, t.w) - fmaxf(gy1, t.y), 0.0f);
                    float inter = w * h;
                    if (inter > 0.0f) {
                        float iou = inter / fmaxf(ga + pa - inter, 1e-6f);
                        float x = sc[(size_t)p * Cn];
                        float ax = fabsf(x);
                        float tt = expf(-ax);
                        float inv = 1.0f / (1.0f + tt);
                        float sig = (x >= 0.0f) ? inv : tt * inv;
                        float i2 = iou * iou;
                        float metric = sig * (i2 * i2 * i2);
                        ins_desc(mv, mi, metric, p);
                    }
                }
            }
        }
#pragma unroll
        for (int k = 0; k < TK; k++) { s_v[tid * TK + k] = mv[k]; s_i[tid * TK + k] = mi[k]; }
        __syncthreads();
        for (int off = 64; off >= 1; off >>= 1) {
            if (tid < off) {
                float ov[TK]; int oi[TK];
                int ia = tid * TK, ib = (tid + off) * TK, i = 0, j = 0;
#pragma unroll
                for (int k = 0; k < TK; k++) {
                    float va = s_v[ia + i], vb = s_v[ib + j];
                    int   na = s_i[ia + i], nb = s_i[ib + j];
                    bool ta = (va > vb) || (va == vb && na < nb);
                    if (ta) { ov[k] = va; oi[k] = na; i++; }
                    else    { ov[k] = vb; oi[k] = nb; j++; }
                }
#pragma unroll
                for (int k = 0; k < TK; k++) { s_v[ia + k] = ov[k]; s_i[ia + k] = oi[k]; }
            }
            __syncthreads();
        }
        if (tid == 0) {
            int np = 0;
#pragma unroll
            for (int k = 0; k < TK; k++) if (s_v[k] > 0.0f) np++;
            s_npos = np;
        }
        __syncthreads();
        if (tid < s_npos) {
            // positives are inside the gt by construction -> pos_mask member
            atomicAdd(&d_fgpre[b * Pn + s_i[tid]], 1);
        }
        if (tid == 0 && s_npos < TK) {
            // zero-metric fill: smallest global indices with metric==0; ing ones count
            int need = TK - s_npos;
            for (int p = 0; p < Pn && need > 0; p++) {
                float4 pr = pr4[p];
                bool ing = (pr.x > gx1) && (pr.x < gx2) && (pr.y > gy1) && (pr.y < gy2);
                bool pos = false;
                if (ing) {
                    float4 t = pb[p];
                    float pa = (t.z - t.x) * (t.w - t.y);
                    float w = fmaxf(fminf(gx2, t.z) - fmaxf(gx1, t.x), 0.0f);
                    float h = fmaxf(fminf(gy2, t.w) - fmaxf(gy1, t.y), 0.0f);
                    float inter = w * h;
                    if (inter > 0.0f) {
                        float iou = inter / fmaxf(ga + pa - inter, 1e-6f);
                        float x = sc[(size_t)p * Cn];
                        float ax = fabsf(x);
                        float tt = expf(-ax);
                        float inv = 1.0f / (1.0f + tt);
                        float sig = (x >= 0.0f) ? inv : tt * inv;
                        float i2 = iou * iou;
                        pos = (sig * (i2 * i2 * i2)) > 0.0f;
                    }
                }
                if (!pos) {
                    need--;
                    if (ing) atomicAdd(&d_fgpre[b * Pn + p], 1);
                }
            }
        }
        __syncthreads();
    }

    // ======== Phase 3: cost min-13 ========
    {
        float cv[TK]; int ci[TK];
#pragma unroll
        for (int k = 0; k < TK; k++) { cv[k] = INFF; ci[k] = 0x7fffffff; }
        const int S = d_invcnt[b];
        const bool fast = (S >= TK);

        if (fast) {
            const float Rr = 11.0013f;  // 3 + log10(1e8) + margin: skipped => cost > 1e8 strictly
#pragma unroll
            for (int lvl = 0; lvl < 3; lvl++) {
                int W = LW[lvl]; float s = LS[lvl]; int base = LBASE[lvl];
                float inv_s = 1.0f / s;
                float fc = cx * inv_s - 0.5f, fr = cy * inv_s - 0.5f;
                int c0 = max(0, (int)floorf(fc - Rr));
                int c1 = min(W - 1, (int)ceilf(fc + Rr));
                int r0 = max(0, (int)floorf(fr - Rr));
                int r1 = min(W - 1, (int)ceilf(fr + Rr));
                int nc = c1 - c0 + 1, nr = r1 - r0 + 1;
                if (nc <= 0 || nr <= 0) continue;
                int tot = nc * nr;
                float lim = Rr * Rr * s * s;
                for (int i = tid; i < tot; i += 128) {
                    int rr = i / nc, cc = i - rr * nc;
                    int col = c0 + cc, row = r0 + rr;
                    int p = base + row * W + col;
                    if (!vm[p]) continue;
                    float px = ((float)col + 0.5f) * s;
                    float py = ((float)row + 0.5f) * s;
                    float dx = px - cx, dy = py - cy;
                    float d2 = dx * dx + dy * dy;
                    if (d2 > lim) continue;
                    float4 t = pb[p];
                    float pa = (t.z - t.x) * (t.w - t.y);
                    float w = fmaxf(fminf(gx2, t.z) - fmaxf(gx1, t.x), 0.0f);
                    float h = fmaxf(fminf(gy2, t.w) - fmaxf(gy1, t.y), 0.0f);
                    float inter = w * h;
                    float iou = inter / fmaxf(ga + pa - inter, 1e-6f);
                    float x = sc[(size_t)p * Cn];
                    float ax = fabsf(x);
                    float tt = expf(-ax);
                    float inv = 1.0f / (1.0f + tt);
                    float sig = (x >= 0.0f) ? inv : tt * inv;
                    float sp = fmaxf(x, 0.0f) + log1pf(tt);
                    float sca = iou - sig;
                    float cls = (sp - x * iou) * (sca * sca);
                    float icst = -3.0f * logf(iou + 1e-7f);
                    float dist = sqrtf(d2) / s;
                    float scp = expf((dist - 3.0f) * 2.302585092994046f);
                    ins_asc(cv, ci, cls + icst + scp, p);
                }
            }
        } else {
            for (int p = tid; p < Pn; p += 128) {
                if (vm[p]) {
                    float4 pr = pr4[p];
                    float4 t = pb[p];
                    float pa = (t.z - t.x) * (t.w - t.y);
                    float w = fmaxf(fminf(gx2, t.z) - fmaxf(gx1, t.x), 0.0f);
                    float h = fmaxf(fminf(gy2, t.w) - fmaxf(gy1, t.y), 0.0f);
                    float inter = w * h;
                    float iou = inter / fmaxf(ga + pa - inter, 1e-6f);
                    float x = sc[(size_t)p * Cn];
                    float ax = fabsf(x);
                    float tt = expf(-ax);
                    float inv = 1.0f / (1.0f + tt);
                    float sig = (x >= 0.0f) ? inv : tt * inv;
                    float sp = fmaxf(x, 0.0f) + log1pf(tt);
                    float sca = iou - sig;
                    float cls = (sp - x * iou) * (sca * sca);
                    float icst = -3.0f * logf(iou + 1e-7f);
                    float dx = pr.x - cx, dy = pr.y - cy;
                    float dist = sqrtf(dx * dx + dy * dy) / pr.z;
                    float scp = expf((dist - 3.0f) * 2.302585092994046f);
                    ins_asc(cv, ci, cls + icst + scp, p);
                } else {
                    ins_asc(cv, ci, 1e8f, p);
                }
            }
        }

#pragma unroll
        for (int k = 0; k < TK; k++) { s_v[tid * TK + k] = cv[k]; s_i[tid * TK + k] = ci[k]; }
        __syncthreads();
        for (int off = 64; off >= 1; off >>= 1) {
            if (tid < off) {
                float ov[TK]; int oi[TK];
                int ia = tid * TK, ib = (tid + off) * TK, i = 0, j = 0;
#pragma unroll
                for (int k = 0; k < TK; k++) {
                    float va = s_v[ia + i], vb = s_v[ib + j];
                    int   na = s_i[ia + i], nb = s_i[ib + j];
                    bool ta = (va < vb) || (va == vb && na < nb);
                    if (ta) { ov[k] = va; oi[k] = na; i++; }
                    else    { ov[k] = vb; oi[k] = nb; j++; }
                }
#pragma unroll
                for (int k = 0; k < TK; k++) { s_v[ia + k] = ov[k]; s_i[ia + k] = oi[k]; }
            }
            __syncthreads();
        }
        if (tid == 0 && fast) {
            // merge candidate list with 13 sentinels (value 1e8, smallest invalid indices)
            float av[TK]; int ai[TK];
#pragma unroll
            for (int k = 0; k < TK; k++) { av[k] = s_v[k]; ai[k] = s_i[k]; }
            int i = 0, j = 0;
#pragma unroll
            for (int k = 0; k < TK; k++) {
                float va = (i < TK) ? av[i] : INFF;
                int   na = (i < TK) ? ai[i] : 0x7fffffff;
                float vb = 1e8f;
                int   nb = d_inv13[b * TK + j];
                bool ta = (va < vb) || (va == vb && na < nb);
                if (ta) { s_v[k] = va; s_i[k] = na; i++; }
                else    { s_v[k] = vb; s_i[k] = nb; j++; }
            }
        }
        __syncthreads();
        if (tid < s_ks) {
            int p = s_i[tid];
            atomicAdd(&d_mcount[b * Pn + p], 1);
            d_mg[b * Pn + p] = g;   // consumed only when count==1
        }
    }
}

// ---------------- final resolution ----------------
__device__ __forceinline__ float cost_of_pair(
    float iou, float x, float d2, float s) {
    float ax  = fabsf(x);
    float t   = expf(-ax);
    float inv = 1.0f / (1.0f + t);
    float sig = (x >= 0.0f) ? inv : t * inv;
    float sp  = fmaxf(x, 0.0f) + log1pf(t);
    float sca = iou - sig;
    float cls = (sp - x * iou) * (sca * sca);
    float icst = -3.0f * logf(iou + 1e-7f);
    float dist = sqrtf(d2) / s;
    float scp  = expf((dist - 3.0f) * 2.302585092994046f);
    return cls + icst + scp;
}

__global__ __launch_bounds__(128) void final_kernel(
    const float* __restrict__ pred_bboxes,
    const float* __restrict__ pred_scores,
    const float* __restrict__ priors,
    const int*   __restrict__ gt_labels,
    const float* __restrict__ gt_bboxes,
    float* __restrict__ out,
    int Pn, int Gn, int Cn, int Bn) {
    int b = blockIdx.y;
    __shared__ float4 sgt[GG];
    __shared__ int    slab[GG];
    for (int i = threadIdx.x; i < Gn; i += blockDim.x) {
        sgt[i]  = reinterpret_cast<const float4*>(gt_bboxes + (size_t)b * Gn * 4)[i];
        slab[i] = gt_labels[b * Gn + i];
    }
    __syncthreads();

    int p = blockIdx.x * blockDim.x + threadIdx.x;
    if (p >= Pn) return;
    int bp = b * Pn + p;
    int BP = Bn * Pn;

    int cnt = d_mcount[bp];
    float lab = 80.0f, metr = 0.0f;
    float ox0 = 0.f, ox1 = 0.f, ox2 = 0.f, ox3 = 0.f;

    if (cnt > 0) {
        float4 pbx = reinterpret_cast<const float4*>(pred_bboxes + (size_t)b * Pn * 4)[p];
        float pa = (pbx.z - pbx.x) * (pbx.w - pbx.y);
        int gsel;
        if (cnt == 1) {
            gsel = d_mg[bp];
        } else if (!d_valid[bp]) {
            gsel = 0;  // all costs tie at 1e8 -> first argmin
        } else {
            float px = priors[p * 4 + 0], py = priors[p * 4 + 1], s = priors[p * 4 + 2];
            float s2 = s * s;
            const float* srow = pred_scores + ((size_t)b * Pn + p) * Cn;
            float best = __int_as_float(0x7f800000);
            float rr2  = __int_as_float(0x7f800000);
            int bg = 0;
            for (int g = 0; g < Gn; g++) {
                float4 gb = sgt[g];
                float gcx = (gb.x + gb.z) * 0.5f, gcy = (gb.y + gb.w) * 0.5f;
                float dx = px - gcx, dy = py - gcy;
                float d2 = dx * dx + dy * dy;
                if (d2 > rr2 * s2) continue;
                float gaa = (gb.z - gb.x) * (gb.w - gb.y);
                float w = fmaxf(fminf(gb.z, pbx.z) - fmaxf(gb.x, pbx.x), 0.0f);
                float h = fmaxf(fminf(gb.w, pbx.w) - fmaxf(gb.y, pbx.y), 0.0f);
                float inter = w * h;
                float iou = inter / fmaxf(gaa + pa - inter, 1e-6f);
                float x = srow[slab[g]];
                float c = cost_of_pair(iou, x, d2, s);
                if (c < best) { best = c; bg = g; rr2 = skip_radius2(best); }
            }
            gsel = bg;
        }
        float4 gb = sgt[gsel];
        float gaa = (gb.z - gb.x) * (gb.w - gb.y);
        float w = fmaxf(fminf(gb.z, pbx.z) - fmaxf(gb.x, pbx.x), 0.0f);
        float h = fmaxf(fminf(gb.w, pbx.w) - fmaxf(gb.y, pbx.y), 0.0f);
        float inter = w * h;
        float iou = inter / fmaxf(gaa + pa - inter, 1e-6f);

        lab = (float)slab[gsel];
        metr = iou;
        ox0 = gb.x; ox1 = gb.y; ox2 = gb.z; ox3 = gb.w;
    }

    out[bp]            = lab;
    out[BP + bp]       = 1.0f;
    out[2 * BP + (size_t)bp * 4 + 0] = ox0;
    out[2 * BP + (size_t)bp * 4 + 1] = ox1;
    out[2 * BP + (size_t)bp * 4 + 2] = ox2;
    out[2 * BP + (size_t)bp * 4 + 3] = ox3;
    out[6 * BP + bp]   = metr;
    out[7 * BP + bp]   = (d_fgpre[bp] > 0) ? 1.0f : 0.0f;
}

// ---------------- launch ----------------
extern "C" void kernel_launch(void* const* d_in, const int* in_sizes, int n_in,
                              void* d_out, int out_size) {
    const float* pred_bboxes = (const float*)d_in[0];
    const float* pred_scores = (const float*)d_in[1];
    const float* priors      = (const float*)d_in[2];
    const int*   gt_labels   = (const int*)  d_in[3];
    const float* gt_bboxes   = (const float*)d_in[4];
    const float* pad         = (const float*)d_in[5];

    int P = in_sizes[2] / 4;
    int B = in_sizes[0] / (P * 4);
    int G = in_sizes[4] / (B * 4);
    int C = in_sizes[1] / (B * P);
    float* out = (float*)d_out;
    int nch = (P + 31) / 32;

    zerobins_kernel<<<(BB * NBIN + 255) / 256, 256>>>();

    dim3 gv((P + 255) / 256, B);
    valid_kernel<<<gv, 256>>>(priors, gt_bboxes, pad, pred_bboxes, P, G);

    inv13_kernel<<<B, 128>>>(P);

    sortscatter_kernel<<<B, 256>>>(pred_bboxes, P);

    dim3 gm(nch, B);
    meta_kernel<<<gm, 32>>>(P);

    dim3 gp(G, B);
    pair_kernel<<<gp, 128>>>(pred_bboxes, pred_scores, priors,
                             gt_labels, gt_bboxes, pad, P, G, C, nch);

    dim3 gf((P + 127) / 128, B);
    final_kernel<<<gf, 128>>>(pred_bboxes, pred_scores, priors,
                              gt_labels, gt_bboxes, out, P, G, C, B);
}

// round 9
// speedup vs baseline: 2.1301x; 1.0812x over previous
#include <cuda_runtime.h>
#include <math.h>
#include <stdint.h>

#define BB 16
#define GG 100
#define PP 8400
#define CC 80
#define TK 13
#define NBIN 64   // 8x8 spatial bins
#define NCHMAX ((PP + 31) / 32)

// ---------------- static scratch ----------------
__device__ int           d_fgpre[BB * PP];
__device__ int           d_mcount[BB * PP];
__device__ int           d_mg[BB * PP];
__device__ unsigned char d_valid[BB * PP];
__device__ float4        d_sorted[BB * PP];
__device__ float4        d_cmeta[BB * NCHMAX];
__device__ int           d_bincnt[BB * NBIN];
__device__ int           d_bincur[BB * NBIN];
__device__ int           d_inv13[BB * TK];
__device__ int           d_invcnt[BB];

// ---------------- sorted-list helpers ----------
template <int N>
__device__ __forceinline__ void ins_desc(float (&V)[N], int (&I)[N], float v, int idx) {
    if (v > V[N - 1] || (v == V[N - 1] && idx < I[N - 1])) {
#pragma unroll
        for (int k = 0; k < N; k++) {
            if (v > V[k] || (v == V[k] && idx < I[k])) {
                float tv = V[k]; int ti = I[k];
                V[k] = v; I[k] = idx;
                v = tv; idx = ti;
            }
        }
    }
}

template <int N>
__device__ __forceinline__ void ins_asc(float (&V)[N], int (&I)[N], float v, int idx) {
    if (v < V[N - 1] || (v == V[N - 1] && idx < I[N - 1])) {
#pragma unroll
        for (int k = 0; k < N; k++) {
            if (v < V[k] || (v == V[k] && idx < I[k])) {
                float tv = V[k]; int ti = I[k];
                V[k] = v; I[k] = idx;
                v = tv; idx = ti;
            }
        }
    }
}

template <int N>
__device__ __forceinline__ void ins_val(float (&V)[N], float v) {
    if (v > V[N - 1]) {
#pragma unroll
        for (int k = 0; k < N; k++) {
            if (v > V[k]) { float tv = V[k]; V[k] = v; v = tv; }
        }
    }
}

__device__ __forceinline__ float skip_radius2(float thr) {
    float rr = 3.0f + log10f(thr + 1e-6f) + 1e-3f;
    if (rr > 0.0f) return rr * rr;
    return (thr < 9e-4f) ? -1.0f : __int_as_float(0x7f800000);
}

__device__ __forceinline__ int binof(float4 t) {
    float xc = 0.5f * (t.x + t.z);
    float yc = 0.5f * (t.y + t.w);
    int bx = min(7, max(0, (int)(xc * (8.0f / 640.0f))));
    int by = min(7, max(0, (int)(yc * (8.0f / 640.0f))));
    return by * 8 + bx;
}

// ---------------- prep kernels ----------------
__global__ void zerobins_kernel() {
    int i = blockIdx.x * blockDim.x + threadIdx.x;
    if (i < BB * NBIN) d_bincnt[i] = 0;
}

__global__ void valid_kernel(const float* __restrict__ priors,
                             const float* __restrict__ gtb,
                             const float* __restrict__ pad,
                             const float* __restrict__ pred_bboxes,
                             int Pn, int Gn) {
    int b = blockIdx.y;
    __shared__ float sgt[GG * 4];
    __shared__ float spad[GG];
    for (int i = threadIdx.x; i < Gn * 4; i += blockDim.x) sgt[i] = gtb[b * Gn * 4 + i];
    for (int i = threadIdx.x; i < Gn; i += blockDim.x)     spad[i] = pad[b * Gn + i];
    __syncthreads();
    int p = blockIdx.x * blockDim.x + threadIdx.x;
    if (p >= Pn) return;
    float px = priors[p * 4 + 0];
    float py = priors[p * 4 + 1];
    unsigned char v = 0;
    for (int g = 0; g < Gn; g++) {
        if (spad[g] != 0.0f) {
            float x1 = sgt[g * 4 + 0], y1 = sgt[g * 4 + 1];
            float x2 = sgt[g * 4 + 2], y2 = sgt[g * 4 + 3];
            if (px > x1 && py > y1 && px < x2 && py < y2) { v = 1; break; }
        }
    }
    int bp = b * Pn + p;
    d_valid[bp]  = v;
    d_fgpre[bp]  = 0;
    d_mcount[bp] = 0;
    float4 t = reinterpret_cast<const float4*>(pred_bboxes)[(size_t)b * Pn + p];
    atomicAdd(&d_bincnt[b * NBIN + binof(t)], 1);
}

__global__ void scan_kernel() {
    int b = blockIdx.x;
    if (threadIdx.x == 0) {
        int acc = 0;
        for (int i = 0; i < NBIN; i++) {
            int c = d_bincnt[b * NBIN + i];
            d_bincur[b * NBIN + i] = acc;
            acc += c;
        }
    }
}

__global__ void scatter_kernel(const float* __restrict__ pred_bboxes, int Pn) {
    int b = blockIdx.y;
    int p = blockIdx.x * blockDim.x + threadIdx.x;
    if (p >= Pn) return;
    float4 t = reinterpret_cast<const float4*>(pred_bboxes)[(size_t)b * Pn + p];
    int pos = atomicAdd(&d_bincur[b * NBIN + binof(t)], 1);
    d_sorted[b * Pn + pos] = t;
}

__global__ void inv13_kernel(int Pn) {
    int b = blockIdx.x, tid = threadIdx.x;
    int lst[TK]; int cnt = 0;
    for (int p = tid; p < Pn && cnt < TK; p += 128)
        if (!d_valid[b * Pn + p]) lst[cnt++] = p;
#pragma unroll
    for (int k = 0; k < TK; k++) if (k >= cnt) lst[k] = 0x7fffffff;
    __shared__ int s_i[128 * TK];
#pragma unroll
    for (int k = 0; k < TK; k++) s_i[tid * TK + k] = lst[k];
    __syncthreads();
    for (int off = 64; off >= 1; off >>= 1) {
        if (tid < off) {
            int oi[TK];
            int ia = tid * TK, ib = (tid + off) * TK, i = 0, j = 0;
#pragma unroll
            for (int k = 0; k < TK; k++) {
                int na = s_i[ia + i], nb = s_i[ib + j];
                if (na <= nb) { oi[k] = na; i++; } else { oi[k] = nb; j++; }
            }
#pragma unroll
            for (int k = 0; k < TK; k++) s_i[ia + k] = oi[k];
        }
        __syncthreads();
    }
    if (tid == 0) {
        int S = 0;
#pragma unroll
        for (int k = 0; k < TK; k++) {
            d_inv13[b * TK + k] = s_i[k];
            if (s_i[k] != 0x7fffffff) S++;
        }
        d_invcnt[b] = S;
    }
}

__global__ void meta_kernel(int Pn) {
    int c = blockIdx.x, b = blockIdx.y, lane = threadIdx.x;
    int p = c * 32 + lane;
    const float INFF = __int_as_float(0x7f800000);
    float x1 = INFF, y1 = INFF, x2 = -INFF, y2 = -INFF;
    if (p < Pn) {
        float4 t = d_sorted[b * Pn + p];
        x1 = t.x; y1 = t.y; x2 = t.z; y2 = t.w;
    }
#pragma unroll
    for (int off = 16; off >= 1; off >>= 1) {
        x1 = fminf(x1, __shfl_down_sync(0xffffffffu, x1, off));
        y1 = fminf(y1, __shfl_down_sync(0xffffffffu, y1, off));
        x2 = fmaxf(x2, __shfl_down_sync(0xffffffffu, x2, off));
        y2 = fmaxf(y2, __shfl_down_sync(0xffffffffu, y2, off));
    }
    if (lane == 0) d_cmeta[b * NCHMAX + c] = make_float4(x1, y1, x2, y2);
}

// ---------------- main pair kernel ----------------
__global__ __launch_bounds__(128) void pair_kernel(
    const float* __restrict__ pred_bboxes,
    const float* __restrict__ pred_scores,
    const float* __restrict__ priors,
    const int*   __restrict__ gt_labels,
    const float* __restrict__ gt_bboxes,
    const float* __restrict__ pad,
    int Pn, int Gn, int Cn, int nch) {
    int g = blockIdx.x, b = blockIdx.y;
    if (pad[b * Gn + g] == 0.0f) return;

    const float gx1 = gt_bboxes[(b * Gn + g) * 4 + 0];
    const float gy1 = gt_bboxes[(b * Gn + g) * 4 + 1];
    const float gx2 = gt_bboxes[(b * Gn + g) * 4 + 2];
    const float gy2 = gt_bboxes[(b * Gn + g) * 4 + 3];
    const int   cid = gt_labels[b * Gn + g];
    const float ga  = (gx2 - gx1) * (gy2 - gy1);
    const float cx  = (gx1 + gx2) * 0.5f;
    const float cy  = (gy1 + gy2) * 0.5f;

    const float4*        pb  = reinterpret_cast<const float4*>(pred_bboxes) + (size_t)b * Pn;
    const float4*        pr4 = reinterpret_cast<const float4*>(priors);
    const float*         sc  = pred_scores + (size_t)b * Pn * Cn + cid;
    const unsigned char* vm  = d_valid + b * Pn;
    const int tid = threadIdx.x;
    const int warp = tid >> 5, lane = tid & 31;
    const float INFF = __int_as_float(0x7f800000);

    __shared__ float s_v[128 * TK];
    __shared__ int   s_i[128 * TK];
    __shared__ int   s_ks;
    __shared__ int   s_npos;

    // ======== Phase 1: top-13 iou over sorted, chunk-skipped preds ========
    {
        float iv[TK];
#pragma unroll
        for (int k = 0; k < TK; k++) iv[k] = -INFF;
        const float4* sp = d_sorted + (size_t)b * Pn;
        const float4* cm = d_cmeta + b * NCHMAX;
        for (int c = warp; c < nch; c += 4) {
            float4 m = cm[c];
            if (m.x < gx2 && m.z > gx1 && m.y < gy2 && m.w > gy1) {
                int p = c * 32 + lane;
                if (p < Pn) {
                    float4 t = sp[p];
                    float pa = (t.z - t.x) * (t.w - t.y);
                    float w = fmaxf(fminf(gx2, t.z) - fmaxf(gx1, t.x), 0.0f);
                    float h = fmaxf(fminf(gy2, t.w) - fmaxf(gy1, t.y), 0.0f);
                    float inter = w * h;
                    float iou = __fdividef(inter, fmaxf(ga + pa - inter, 1e-6f));
                    ins_val(iv, iou);
                }
            }
        }
#pragma unroll
        for (int k = 0; k < TK; k++) s_v[tid * TK + k] = iv[k];
        __syncthreads();
        for (int off = 64; off >= 1; off >>= 1) {
            if (tid < off) {
                float ov[TK];
                int ia = tid * TK, ib = (tid + off) * TK, i = 0, j = 0;
#pragma unroll
                for (int k = 0; k < TK; k++) {
                    float va = s_v[ia + i], vb = s_v[ib + j];
                    if (va >= vb) { ov[k] = va; i++; } else { ov[k] = vb; j++; }
                }
#pragma unroll
                for (int k = 0; k < TK; k++) s_v[ia + k] = ov[k];
            }
            __syncthreads();
        }
        if (tid == 0) {
            float sum = 0.0f;
#pragma unroll
            for (int k = 0; k < TK; k++) sum += fmaxf(s_v[k], 0.0f);  // skipped pairs are iou==0
            int ks = (int)sum;
            if (ks < 1) ks = 1;
            if (ks > TK) ks = TK;
            s_ks = ks;
        }
        __syncthreads();
    }

    const int   LW[3] = {80, 40, 20};
    const float LS[3] = {8.0f, 16.0f, 32.0f};
    const int   LBASE[3] = {0, 6400, 8000};

    // ======== Phase 2: metric top-13 via gt-box grid rectangle ========
    {
        float mv[TK]; int mi[TK];
#pragma unroll
        for (int k = 0; k < TK; k++) { mv[k] = -INFF; mi[k] = 0x7fffffff; }
#pragma unroll
        for (int lvl = 0; lvl < 3; lvl++) {
            int W = LW[lvl]; float s = LS[lvl]; int base = LBASE[lvl];
            float inv_s = 1.0f / s;
            int c0 = max(0, (int)floorf(gx1 * inv_s - 0.5f));
            int c1 = min(W - 1, (int)ceilf(gx2 * inv_s - 0.5f));
            int r0 = max(0, (int)floorf(gy1 * inv_s - 0.5f));
            int r1 = min(W - 1, (int)ceilf(gy2 * inv_s - 0.5f));
            int nc = c1 - c0 + 1, nr = r1 - r0 + 1;
            if (nc <= 0 || nr <= 0) continue;
            int tot = nc * nr;
            for (int i = tid; i < tot; i += 128) {
                int rr = i / nc, cc = i - rr * nc;
                int col = c0 + cc, row = r0 + rr;
                float px = ((float)col + 0.5f) * s;
                float py = ((float)row + 0.5f) * s;
                if (px > gx1 && px < gx2 && py > gy1 && py < gy2) {
                    int p = base + row * W + col;
                    float4 t = pb[p];
                    float pa = (t.z - t.x) * (t.w - t.y);
                    float w = fmaxf(fminf(gx2, t.z) - fmaxf(gx1, t.x), 0.0f);
                    float h = fmaxf(fminf(gy2, t.w) - fmaxf(gy1, t.y), 0.0f);
                    float inter = w * h;
                    if (inter > 0.0f) {
                        float iou = inter / fmaxf(ga + pa - inter, 1e-6f);
                        float x = sc[(size_t)p * Cn];
                        float ax = fabsf(x);
                        float tt = expf(-ax);
                        float inv = 1.0f / (1.0f + tt);
                        float sig = (x >= 0.0f) ? inv : tt * inv;
                        float i2 = iou * iou;
                        float metric = sig * (i2 * i2 * i2);
                        ins_desc(mv, mi, metric, p);
                    }
                }
            }
        }
#pragma unroll
        for (int k = 0; k < TK; k++) { s_v[tid * TK + k] = mv[k]; s_i[tid * TK + k] = mi[k]; }
        __syncthreads();
        for (int off = 64; off >= 1; off >>= 1) {
            if (tid < off) {
                float ov[TK]; int oi[TK];
                int ia = tid * TK, ib = (tid + off) * TK, i = 0, j = 0;
#pragma unroll
                for (int k = 0; k < TK; k++) {
                    float va = s_v[ia + i], vb = s_v[ib + j];
                    int   na = s_i[ia + i], nb = s_i[ib + j];
                    bool ta = (va > vb) || (va == vb && na < nb);
                    if (ta) { ov[k] = va; oi[k] = na; i++; }
                    else    { ov[k] = vb; oi[k] = nb; j++; }
                }
#pragma unroll
                for (int k = 0; k < TK; k++) { s_v[ia + k] = ov[k]; s_i[ia + k] = oi[k]; }
            }
            __syncthreads();
        }
        if (tid == 0) {
            int np = 0;
#pragma unroll
            for (int k = 0; k < TK; k++) if (s_v[k] > 0.0f) np++;
            s_npos = np;
        }
        __syncthreads();
        if (tid < s_npos) {
            atomicAdd(&d_fgpre[b * Pn + s_i[tid]], 1);
        }
        if (tid == 0 && s_npos < TK) {
            // zero-metric fill: smallest global indices with metric==0; ing ones count
            int need = TK - s_npos;
            for (int p = 0; p < Pn && need > 0; p++) {
                float4 pr = pr4[p];
                bool ing = (pr.x > gx1) && (pr.x < gx2) && (pr.y > gy1) && (pr.y < gy2);
                bool pos = false;
                if (ing) {
                    float4 t = pb[p];
                    float pa = (t.z - t.x) * (t.w - t.y);
                    float w = fmaxf(fminf(gx2, t.z) - fmaxf(gx1, t.x), 0.0f);
                    float h = fmaxf(fminf(gy2, t.w) - fmaxf(gy1, t.y), 0.0f);
                    float inter = w * h;
                    if (inter > 0.0f) {
                        float iou = inter / fmaxf(ga + pa - inter, 1e-6f);
                        float x = sc[(size_t)p * Cn];
                        float ax = fabsf(x);
                        float tt = expf(-ax);
                        float inv = 1.0f / (1.0f + tt);
                        float sig = (x >= 0.0f) ? inv : tt * inv;
                        float i2 = iou * iou;
                        pos = (sig * (i2 * i2 * i2)) > 0.0f;
                    }
                }
                if (!pos) {
                    need--;
                    if (ing) atomicAdd(&d_fgpre[b * Pn + p], 1);
                }
            }
        }
        __syncthreads();
    }

    // ======== Phase 3: cost min-13 ========
    {
        float cv[TK]; int ci[TK];
#pragma unroll
        for (int k = 0; k < TK; k++) { cv[k] = INFF; ci[k] = 0x7fffffff; }
        const int S = d_invcnt[b];
        const bool fast = (S >= TK);

        if (fast) {
            const float Rr = 11.0013f;  // 3 + log10(1e8) + margin
#pragma unroll
            for (int lvl = 0; lvl < 3; lvl++) {
                int W = LW[lvl]; float s = LS[lvl]; int base = LBASE[lvl];
                float inv_s = 1.0f / s;
                float fc = cx * inv_s - 0.5f, fr = cy * inv_s - 0.5f;
                int c0 = max(0, (int)floorf(fc - Rr));
                int c1 = min(W - 1, (int)ceilf(fc + Rr));
                int r0 = max(0, (int)floorf(fr - Rr));
                int r1 = min(W - 1, (int)ceilf(fr + Rr));
                int nc = c1 - c0 + 1, nr = r1 - r0 + 1;
                if (nc <= 0 || nr <= 0) continue;
                int tot = nc * nr;
                float lim = Rr * Rr * s * s;
                for (int i = tid; i < tot; i += 128) {
                    int rr = i / nc, cc = i - rr * nc;
                    int col = c0 + cc, row = r0 + rr;
                    int p = base + row * W + col;
                    if (!vm[p]) continue;
                    float px = ((float)col + 0.5f) * s;
                    float py = ((float)row + 0.5f) * s;
                    float dx = px - cx, dy = py - cy;
                    float d2 = dx * dx + dy * dy;
                    if (d2 > lim) continue;
                    float4 t = pb[p];
                    float pa = (t.z - t.x) * (t.w - t.y);
                    float w = fmaxf(fminf(gx2, t.z) - fmaxf(gx1, t.x), 0.0f);
                    float h = fmaxf(fminf(gy2, t.w) - fmaxf(gy1, t.y), 0.0f);
                    float inter = w * h;
                    float iou = inter / fmaxf(ga + pa - inter, 1e-6f);
                    float x = sc[(size_t)p * Cn];
                    float ax = fabsf(x);
                    float tt = expf(-ax);
                    float inv = 1.0f / (1.0f + tt);
                    float sig = (x >= 0.0f) ? inv : tt * inv;
                    float sp = fmaxf(x, 0.0f) + log1pf(tt);
                    float sca = iou - sig;
                    float cls = (sp - x * iou) * (sca * sca);
                    float icst = -3.0f * logf(iou + 1e-7f);
                    float dist = sqrtf(d2) / s;
                    float scp = expf((dist - 3.0f) * 2.302585092994046f);
                    ins_asc(cv, ci, cls + icst + scp, p);
                }
            }
        } else {
            for (int p = tid; p < Pn; p += 128) {
                if (vm[p]) {
                    float4 pr = pr4[p];
                    float4 t = pb[p];
                    float pa = (t.z - t.x) * (t.w - t.y);
                    float w = fmaxf(fminf(gx2, t.z) - fmaxf(gx1, t.x), 0.0f);
                    float h = fmaxf(fminf(gy2, t.w) - fmaxf(gy1, t.y), 0.0f);
                    float inter = w * h;
                    float iou = inter / fmaxf(ga + pa - inter, 1e-6f);
                    float x = sc[(size_t)p * Cn];
                    float ax = fabsf(x);
                    float tt = expf(-ax);
                    float inv = 1.0f / (1.0f + tt);
                    float sig = (x >= 0.0f) ? inv : tt * inv;
                    float sp = fmaxf(x, 0.0f) + log1pf(tt);
                    float sca = iou - sig;
                    float cls = (sp - x * iou) * (sca * sca);
                    float icst = -3.0f * logf(iou + 1e-7f);
                    float dx = pr.x - cx, dy = pr.y - cy;
                    float dist = sqrtf(dx * dx + dy * dy) / pr.z;
                    float scp = expf((dist - 3.0f) * 2.302585092994046f);
                    ins_asc(cv, ci, cls + icst + scp, p);
                } else {
                    ins_asc(cv, ci, 1e8f, p);
                }
            }
        }

#pragma unroll
        for (int k = 0; k < TK; k++) { s_v[tid * TK + k] = cv[k]; s_i[tid * TK + k] = ci[k]; }
        __syncthreads();
        for (int off = 64; off >= 1; off >>= 1) {
            if (tid < off) {
                float ov[TK]; int oi[TK];
                int ia = tid * TK, ib = (tid + off) * TK, i = 0, j = 0;
#pragma unroll
                for (int k = 0; k < TK; k++) {
                    float va = s_v[ia + i], vb = s_v[ib + j];
                    int   na = s_i[ia + i], nb = s_i[ib + j];
                    bool ta = (va < vb) || (va == vb && na < nb);
                    if (ta) { ov[k] = va; oi[k] = na; i++; }
                    else    { ov[k] = vb; oi[k] = nb; j++; }
                }
#pragma unroll
                for (int k = 0; k < TK; k++) { s_v[ia + k] = ov[k]; s_i[ia + k] = oi[k]; }
            }
            __syncthreads();
        }
        if (tid == 0 && fast) {
            float av[TK]; int ai[TK];
#pragma unroll
            for (int k = 0; k < TK; k++) { av[k] = s_v[k]; ai[k] = s_i[k]; }
            int i = 0, j = 0;
#pragma unroll
            for (int k = 0; k < TK; k++) {
                float va = (i < TK) ? av[i] : INFF;
                int   na = (i < TK) ? ai[i] : 0x7fffffff;
                float vb = 1e8f;
                int   nb = d_inv13[b * TK + j];
                bool ta = (va < vb) || (va == vb && na < nb);
                if (ta) { s_v[k] = va; s_i[k] = na; i++; }
                else    { s_v[k] = vb; s_i[k] = nb; j++; }
            }
        }
        __syncthreads();
        if (tid < s_ks) {
            int p = s_i[tid];
            atomicAdd(&d_mcount[b * Pn + p], 1);
            d_mg[b * Pn + p] = g;
        }
    }
}

// ---------------- final resolution ----------------
__device__ __forceinline__ float cost_of_pair(
    float iou, float x, float d2, float s) {
    float ax  = fabsf(x);
    float t   = expf(-ax);
    float inv = 1.0f / (1.0f + t);
    float sig = (x >= 0.0f) ? inv : t * inv;
    float sp  = fmaxf(x, 0.0f) + log1pf(t);
    float sca = iou - sig;
    float cls = (sp - x * iou) * (sca * sca);
    float icst = -3.0f * logf(iou + 1e-7f);
    float dist = sqrtf(d2) / s;
    float scp  = expf((dist - 3.0f) * 2.302585092994046f);
    return cls + icst + scp;
}

__global__ __launch_bounds__(128) void final_kernel(
    const float* __restrict__ pred_bboxes,
    const float* __restrict__ pred_scores,
    const float* __restrict__ priors,
    const int*   __restrict__ gt_labels,
    const float* __restrict__ gt_bboxes,
    float* __restrict__ out,
    int Pn, int Gn, int Cn, int Bn) {
    int b = blockIdx.y;
    __shared__ float4 sgt[GG];
    __shared__ int    slab[GG];
    for (int i = threadIdx.x; i < Gn; i += blockDim.x) {
        sgt[i]  = reinterpret_cast<const float4*>(gt_bboxes + (size_t)b * Gn * 4)[i];
        slab[i] = gt_labels[b * Gn + i];
    }
    __syncthreads();

    int p = blockIdx.x * blockDim.x + threadIdx.x;
    if (p >= Pn) return;
    int bp = b * Pn + p;
    int BP = Bn * Pn;

    int cnt = d_mcount[bp];
    float lab = 80.0f, metr = 0.0f;
    float ox0 = 0.f, ox1 = 0.f, ox2 = 0.f, ox3 = 0.f;

    if (cnt > 0) {
        float4 pbx = reinterpret_cast<const float4*>(pred_bboxes + (size_t)b * Pn * 4)[p];
        float pa = (pbx.z - pbx.x) * (pbx.w - pbx.y);
        int gsel;
        if (cnt == 1) {
            gsel = d_mg[bp];
        } else if (!d_valid[bp]) {
            gsel = 0;
        } else {
            float px = priors[p * 4 + 0], py = priors[p * 4 + 1], s = priors[p * 4 + 2];
            float s2 = s * s;
            const float* srow = pred_scores + ((size_t)b * Pn + p) * Cn;
            float best = __int_as_float(0x7f800000);
            float rr2  = __int_as_float(0x7f800000);
            int bg = 0;
            for (int g = 0; g < Gn; g++) {
                float4 gb = sgt[g];
                float gcx = (gb.x + gb.z) * 0.5f, gcy = (gb.y + gb.w) * 0.5f;
                float dx = px - gcx, dy = py - gcy;
                float d2 = dx * dx + dy * dy;
                if (d2 > rr2 * s2) continue;
                float gaa = (gb.z - gb.x) * (gb.w - gb.y);
                float w = fmaxf(fminf(gb.z, pbx.z) - fmaxf(gb.x, pbx.x), 0.0f);
                float h = fmaxf(fminf(gb.w, pbx.w) - fmaxf(gb.y, pbx.y), 0.0f);
                float inter = w * h;
                float iou = inter / fmaxf(gaa + pa - inter, 1e-6f);
                float x = srow[slab[g]];
                float c = cost_of_pair(iou, x, d2, s);
                if (c < best) { best = c; bg = g; rr2 = skip_radius2(best); }
            }
            gsel = bg;
        }
        float4 gb = sgt[gsel];
        float gaa = (gb.z - gb.x) * (gb.w - gb.y);
        float w = fmaxf(fminf(gb.z, pbx.z) - fmaxf(gb.x, pbx.x), 0.0f);
        float h = fmaxf(fminf(gb.w, pbx.w) - fmaxf(gb.y, pbx.y), 0.0f);
        float inter = w * h;
        float iou = inter / fmaxf(gaa + pa - inter, 1e-6f);

        lab = (float)slab[gsel];
        metr = iou;
        ox0 = gb.x; ox1 = gb.y; ox2 = gb.z; ox3 = gb.w;
    }

    out[bp]            = lab;
    out[BP + bp]       = 1.0f;
    out[2 * BP + (size_t)bp * 4 + 0] = ox0;
    out[2 * BP + (size_t)bp * 4 + 1] = ox1;
    out[2 * BP + (size_t)bp * 4 + 2] = ox2;
    out[2 * BP + (size_t)bp * 4 + 3] = ox3;
    out[6 * BP + bp]   = metr;
    out[7 * BP + bp]   = (d_fgpre[bp] > 0) ? 1.0f : 0.0f;
}

// ---------------- launch ----------------
extern "C" void kernel_launch(void* const* d_in, const int* in_sizes, int n_in,
                              void* d_out, int out_size) {
    const float* pred_bboxes = (const float*)d_in[0];
    const float* pred_scores = (const float*)d_in[1];
    const float* priors      = (const float*)d_in[2];
    const int*   gt_labels   = (const int*)  d_in[3];
    const float* gt_bboxes   = (const float*)d_in[4];
    const float* pad         = (const float*)d_in[5];

    int P = in_sizes[2] / 4;
    int B = in_sizes[0] / (P * 4);
    int G = in_sizes[4] / (B * 4);
    int C = in_sizes[1] / (B * P);
    float* out = (float*)d_out;
    int nch = (P + 31) / 32;

    zerobins_kernel<<<(BB * NBIN + 255) / 256, 256>>>();

    dim3 gv((P + 255) / 256, B);
    valid_kernel<<<gv, 256>>>(priors, gt_bboxes, pad, pred_bboxes, P, G);

    inv13_kernel<<<B, 128>>>(P);

    scan_kernel<<<B, 32>>>();

    dim3 gs((P + 255) / 256, B);
    scatter_kernel<<<gs, 256>>>(pred_bboxes, P);

    dim3 gm(nch, B);
    meta_kernel<<<gm, 32>>>(P);

    dim3 gp(G, B);
    pair_kernel<<<gp, 128>>>(pred_bboxes, pred_scores, priors,
                             gt_labels, gt_bboxes, pad, P, G, C, nch);

    dim3 gf((P + 127) / 128, B);
    final_kernel<<<gf, 128>>>(pred_bboxes, pred_scores, priors,
                              gt_labels, gt_bboxes, out, P, G, C, B);
}